// round 3
// baseline (speedup 1.0000x reference)
#include <cuda_runtime.h>
#include <math.h>

#define BT      4096
#define KK      64
#define DD      256
#define PP      4
#define KPP     16
#define ROWS    16
#define THREADS 256
#define COLS    1024

typedef unsigned long long ULL;

// u scratch, packed row-pairs: [group][p][rowpair][col] as float2 (ULL)
__device__ __align__(16) float u_scratch[(size_t)BT * COLS];

__device__ __forceinline__ void fma2(ULL &acc, ULL a, ULL b) {
    asm("fma.rn.f32x2 %0, %1, %2, %0;" : "+l"(acc) : "l"(a), "l"(b));
}
__device__ __forceinline__ ULL pack2(float lo, float hi) {
    ULL r; asm("mov.b64 %0, {%1, %2};" : "=l"(r) : "f"(lo), "f"(hi)); return r;
}
__device__ __forceinline__ void unpack2(ULL a, float &lo, float &hi) {
    asm("mov.b64 {%0, %1}, %2;" : "=f"(lo), "=f"(hi) : "l"(a));
}
__device__ __forceinline__ ULL mul2(ULL a, ULL b) {
    ULL r; asm("mul.rn.f32x2 %0, %1, %2;" : "=l"(r) : "l"(a), "l"(b)); return r;
}
__device__ __forceinline__ ULL add2(ULL a, ULL b) {
    ULL r; asm("add.rn.f32x2 %0, %1, %2;" : "=l"(r) : "l"(a), "l"(b)); return r;
}

// ===================== Kernel A: weighted segment-sum (HBM stream) ==========
__global__ __launch_bounds__(256)
void fs_phase1(const float* __restrict__ E_S, const float* __restrict__ W,
               const int* __restrict__ part_idx)
{
    __shared__ float w_s[2 * KK];
    __shared__ float winv_s[2 * PP];
    __shared__ int   pidx_s[KK];

    const int tid = threadIdx.x;
    const int bx  = blockIdx.x;
    const int row0 = bx * 2;

    if (tid < KK)  pidx_s[tid] = part_idx[tid];
    if (tid < 2 * KK) w_s[tid] = W[(size_t)row0 * KK + tid];
    __syncthreads();
    if (tid < 2 * PP) {
        int r = tid >> 2, p = tid & 3;
        float s = 0.f;
#pragma unroll
        for (int kp = 0; kp < KPP; kp++) s += w_s[r * KK + pidx_s[p * KPP + kp]];
        winv_s[tid] = 1.0f / (s + 1e-6f);
    }
    __syncthreads();

    const int p0 = tid >> 6;
    const int d4 = tid & 63;
    const float4* Ea = (const float4*)(E_S + (size_t)row0 * KK * DD);
    const float4* Eb = Ea + (KK * DD / 4);

    float4 aa = make_float4(0.f,0.f,0.f,0.f);
    float4 ab = make_float4(0.f,0.f,0.f,0.f);
#pragma unroll
    for (int kp = 0; kp < KPP; kp++) {
        const int k  = pidx_s[p0 * KPP + kp];
        const float wa = w_s[k];
        const float wb = w_s[KK + k];
        const float4 ea = Ea[k * 64 + d4];
        const float4 eb = Eb[k * 64 + d4];
        aa.x = fmaf(wa, ea.x, aa.x); aa.y = fmaf(wa, ea.y, aa.y);
        aa.z = fmaf(wa, ea.z, aa.z); aa.w = fmaf(wa, ea.w, aa.w);
        ab.x = fmaf(wb, eb.x, ab.x); ab.y = fmaf(wb, eb.y, ab.y);
        ab.z = fmaf(wb, eb.z, ab.z); ab.w = fmaf(wb, eb.w, ab.w);
    }
    const float iva = winv_s[p0];
    const float ivb = winv_s[PP + p0];

    float4 s0 = make_float4(aa.x * iva, ab.x * ivb, aa.y * iva, ab.y * ivb);
    float4 s1 = make_float4(aa.z * iva, ab.z * ivb, aa.w * iva, ab.w * ivb);

    const size_t group = bx >> 3;
    const int    r2g   = bx & 7;
    float4* out4 = ((float4*)u_scratch) + group * 4096 + (size_t)(p0 * 8 + r2g) * 128 + d4 * 2;
    out4[0] = s0;
    out4[1] = s1;
}

// ===================== Kernel B: register-blocked FFMA2 GEMMs ===============
// smem: u_ull[4][8][256] ULL (64KB) | S_s[8][256] ULL (16KB) | alpha[64]f | red[256]f
#define SMEMB_BYTES (8192 * 8 + 2048 * 8 + (64 + 256) * 4)

__global__ __launch_bounds__(THREADS)
void fs_phase2(const float* __restrict__ part_W, const float* __restrict__ part_b,
               const float* __restrict__ v, const float* __restrict__ c,
               const float* __restrict__ ln_g, const float* __restrict__ ln_b,
               const float* __restrict__ proj_W, const float* __restrict__ proj_b,
               const float* __restrict__ out_g, const float* __restrict__ out_b,
               float* __restrict__ out)
{
    extern __shared__ ULL u_ull[];                 // [P][8][256]
    ULL*   S_s     = u_ull + 8192;                 // [8][256]
    float* alpha_s = (float*)(S_s + 2048);         // [16][4]
    float* red_s   = alpha_s + 64;                 // [16][8][2]

    const int tid = threadIdx.x;
    const int bt0 = blockIdx.x * ROWS;

    const int h = tid >> 7;          // row-pair half (rowpairs h*4 .. h*4+3)
    const int g = (tid >> 2) & 31;   // column group (8 cols)
    const int k = tid & 3;           // K-split lane (interleaved)

    // ---- stage u tile (L2-hot) into smem ----
    {
        const float4* gsrc = ((const float4*)u_scratch) + (size_t)blockIdx.x * 4096;
        float4* u4s = (float4*)u_ull;
#pragma unroll
        for (int n = 0; n < 16; n++) u4s[tid + n * 256] = gsrc[tid + n * 256];
    }
    __syncthreads();

    // ---- 2a: per-part linear, register-tiled (4rp x 8col), K interleave x4 --
#pragma unroll 1
    for (int p = 0; p < PP; p++) {
        ULL acc[4][8];
#pragma unroll
        for (int cc = 0; cc < 8; cc++) {
            const float b = (k == 0) ? part_b[p * DD + g * 8 + cc] : 0.f;
            const ULL bp = pack2(b, b);
#pragma unroll
            for (int rp = 0; rp < 4; rp++) acc[rp][cc] = bp;
        }

        const ULL*   ub = u_ull + (p * 8 + h * 4) * 256;
        const float* wb = part_W + (size_t)p * DD * DD + (size_t)(g * 8) * DD;

#pragma unroll 4
        for (int ii = 0; ii < 32; ii++) {
            const int ip = k + 4 * ii;           // i-pair, i = 2*ip
            ulonglong2 uv[4];
#pragma unroll
            for (int rp = 0; rp < 4; rp++)
                uv[rp] = *(const ulonglong2*)(ub + rp * 256 + 2 * ip);
#pragma unroll
            for (int cc = 0; cc < 8; cc++) {
                const float2 wv = *(const float2*)(wb + cc * DD + 2 * ip);
                const ULL w0 = pack2(wv.x, wv.x);
                const ULL w1 = pack2(wv.y, wv.y);
#pragma unroll
                for (int rp = 0; rp < 4; rp++) {
                    fma2(acc[rp][cc], uv[rp].x, w0);
                    fma2(acc[rp][cc], uv[rp].y, w1);
                }
            }
        }
        // K-split reduction over the 4 lanes (xor 1, xor 2)
#pragma unroll
        for (int rp = 0; rp < 4; rp++)
#pragma unroll
            for (int cc = 0; cc < 8; cc++) {
                acc[rp][cc] = add2(acc[rp][cc], __shfl_xor_sync(0xffffffffu, acc[rp][cc], 1));
                acc[rp][cc] = add2(acc[rp][cc], __shfl_xor_sync(0xffffffffu, acc[rp][cc], 2));
            }
        __syncthreads();
        {   // lane k writes rowpair h*4+k
            ULL* dst = u_ull + (p * 8 + h * 4 + k) * 256 + g * 8;
#pragma unroll
            for (int cc = 0; cc < 8; cc++) dst[cc] = acc[k][cc];
        }
        __syncthreads();
    }

    // ---- 2b: LN stats + sigmoid gate per (row, part); one warp per pair ----
    {
        const int wid = tid >> 5, lane = tid & 31;
        const float* uh = (const float*)u_ull;
#pragma unroll 1
        for (int j = 0; j < 8; j++) {
            const int pair = wid * 8 + j;
            const int r = pair >> 2, p = pair & 3;
            const int base = ((p * 8 + (r >> 1)) * 256) * 2 + (r & 1);
            float s1 = 0.f, s2 = 0.f, s3 = 0.f, s4 = 0.f, s5 = 0.f;
#pragma unroll
            for (int i = 0; i < DD / 32; i++) {
                const int col = lane + i * 32;
                const float x  = uh[base + col * 2];
                const float vv = v[p * DD + col];
                const float gv = ln_g[p * DD + col] * vv;
                const float bv = ln_b[p * DD + col] * vv;
                s1 += x; s2 += x * x; s3 += x * gv; s4 += gv; s5 += bv;
            }
#pragma unroll
            for (int off = 16; off; off >>= 1) {
                s1 += __shfl_xor_sync(0xffffffffu, s1, off);
                s2 += __shfl_xor_sync(0xffffffffu, s2, off);
                s3 += __shfl_xor_sync(0xffffffffu, s3, off);
                s4 += __shfl_xor_sync(0xffffffffu, s4, off);
                s5 += __shfl_xor_sync(0xffffffffu, s5, off);
            }
            if (lane == 0) {
                const float m   = s1 * (1.0f / DD);
                const float var = s2 * (1.0f / DD) - m * m;
                const float rs  = rsqrtf(var + 1e-5f);
                const float dot = rs * (s3 - m * s4) + s5 + c[p];
                alpha_s[r * PP + p] = 1.0f / (1.0f + __expf(-dot));
            }
        }
    }
    __syncthreads();

    // ---- scale u_hat by alpha in place ----
#pragma unroll
    for (int p = 0; p < PP; p++) {
#pragma unroll
        for (int r2 = 0; r2 < 8; r2++) {
            const ULL ap = pack2(alpha_s[(2 * r2) * PP + p], alpha_s[(2 * r2 + 1) * PP + p]);
            const int idx = (p * 8 + r2) * 256 + tid;
            u_ull[idx] = mul2(u_ull[idx], ap);
        }
    }
    __syncthreads();

    // ---- 2c: projection, register-tiled (4rp x 8col), K interleave x4 ------
    {
        ULL acc[4][8];
#pragma unroll
        for (int cc = 0; cc < 8; cc++) {
            const float b = (k == 0) ? proj_b[g * 8 + cc] : 0.f;
            const ULL bp = pack2(b, b);
#pragma unroll
            for (int rp = 0; rp < 4; rp++) acc[rp][cc] = bp;
        }

#pragma unroll 1
        for (int p = 0; p < PP; p++) {
            const ULL*   zb = u_ull + (p * 8 + h * 4) * 256;
            const float* wb = proj_W + (size_t)(g * 8) * COLS + p * DD;
#pragma unroll 4
            for (int ii = 0; ii < 32; ii++) {
                const int ip = k + 4 * ii;
                ulonglong2 uv[4];
#pragma unroll
                for (int rp = 0; rp < 4; rp++)
                    uv[rp] = *(const ulonglong2*)(zb + rp * 256 + 2 * ip);
#pragma unroll
                for (int cc = 0; cc < 8; cc++) {
                    const float2 wv = *(const float2*)(wb + (size_t)cc * COLS + 2 * ip);
                    const ULL w0 = pack2(wv.x, wv.x);
                    const ULL w1 = pack2(wv.y, wv.y);
#pragma unroll
                    for (int rp = 0; rp < 4; rp++) {
                        fma2(acc[rp][cc], uv[rp].x, w0);
                        fma2(acc[rp][cc], uv[rp].y, w1);
                    }
                }
            }
        }
#pragma unroll
        for (int rp = 0; rp < 4; rp++)
#pragma unroll
            for (int cc = 0; cc < 8; cc++) {
                acc[rp][cc] = add2(acc[rp][cc], __shfl_xor_sync(0xffffffffu, acc[rp][cc], 1));
                acc[rp][cc] = add2(acc[rp][cc], __shfl_xor_sync(0xffffffffu, acc[rp][cc], 2));
            }
        {   // lane k writes rowpair h*4+k of S
            ULL* dst = S_s + (h * 4 + k) * 256 + g * 8;
#pragma unroll
            for (int cc = 0; cc < 8; cc++) dst[cc] = acc[k][cc];
        }
    }
    __syncthreads();

    // ---- 2d: final LayerNorm across D (thread = column) ----
    {
        float x[ROWS];
#pragma unroll
        for (int r2 = 0; r2 < 8; r2++) unpack2(S_s[r2 * 256 + tid], x[2 * r2], x[2 * r2 + 1]);

        const int wid = tid >> 5, lane = tid & 31;
#pragma unroll
        for (int r = 0; r < ROWS; r++) {
            float s1 = x[r];
            float s2 = x[r] * x[r];
#pragma unroll
            for (int off = 16; off; off >>= 1) {
                s1 += __shfl_xor_sync(0xffffffffu, s1, off);
                s2 += __shfl_xor_sync(0xffffffffu, s2, off);
            }
            if (lane == 0) {
                red_s[(r * 8 + wid) * 2 + 0] = s1;
                red_s[(r * 8 + wid) * 2 + 1] = s2;
            }
        }
        __syncthreads();
        const float og = out_g[tid], ob = out_b[tid];
#pragma unroll
        for (int r = 0; r < ROWS; r++) {
            float s1 = 0.f, s2 = 0.f;
#pragma unroll
            for (int w = 0; w < 8; w++) {
                s1 += red_s[(r * 8 + w) * 2 + 0];
                s2 += red_s[(r * 8 + w) * 2 + 1];
            }
            const float m   = s1 * (1.0f / DD);
            const float var = s2 * (1.0f / DD) - m * m;
            const float rs  = rsqrtf(var + 1e-5f);
            out[(size_t)(bt0 + r) * DD + tid] = (x[r] - m) * rs * og + ob;
        }
    }
}

extern "C" void kernel_launch(void* const* d_in, const int* in_sizes, int n_in,
                              void* d_out, int out_size)
{
    (void)in_sizes; (void)n_in; (void)out_size;
    const float* E_S    = (const float*)d_in[0];
    const float* W      = (const float*)d_in[1];
    const int*   pidx   = (const int*)  d_in[2];
    const float* part_W = (const float*)d_in[3];
    const float* part_b = (const float*)d_in[4];
    const float* v      = (const float*)d_in[5];
    const float* c      = (const float*)d_in[6];
    const float* ln_g   = (const float*)d_in[7];
    const float* ln_b   = (const float*)d_in[8];
    const float* proj_W = (const float*)d_in[9];
    const float* proj_b = (const float*)d_in[10];
    const float* out_g  = (const float*)d_in[11];
    const float* out_b  = (const float*)d_in[12];
    float* out = (float*)d_out;

    fs_phase1<<<BT / 2, 256>>>(E_S, W, pidx);

    cudaFuncSetAttribute(fs_phase2, cudaFuncAttributeMaxDynamicSharedMemorySize, SMEMB_BYTES);
    fs_phase2<<<BT / ROWS, THREADS, SMEMB_BYTES>>>(
        part_W, part_b, v, c, ln_g, ln_b,
        proj_W, proj_b, out_g, out_b, out);
}

// round 4
// speedup vs baseline: 1.0011x; 1.0011x over previous
#include <cuda_runtime.h>
#include <math.h>

#define BT      4096
#define KK      64
#define DD      256
#define PP      4
#define KPP     16
#define ROWS    16
#define THREADS 256
#define COLS    1024

typedef unsigned long long ULL;

// u scratch, packed row-pairs: [group][p][rowpair][col] as float2 (ULL)
__device__ __align__(16) float u_scratch[(size_t)BT * COLS];

__device__ __forceinline__ void fma2(ULL &acc, ULL a, ULL b) {
    asm("fma.rn.f32x2 %0, %1, %2, %0;" : "+l"(acc) : "l"(a), "l"(b));
}
__device__ __forceinline__ ULL pack2(float lo, float hi) {
    ULL r; asm("mov.b64 %0, {%1, %2};" : "=l"(r) : "f"(lo), "f"(hi)); return r;
}
__device__ __forceinline__ void unpack2(ULL a, float &lo, float &hi) {
    asm("mov.b64 {%0, %1}, %2;" : "=f"(lo), "=f"(hi) : "l"(a));
}
__device__ __forceinline__ ULL mul2(ULL a, ULL b) {
    ULL r; asm("mul.rn.f32x2 %0, %1, %2;" : "=l"(r) : "l"(a), "l"(b)); return r;
}
__device__ __forceinline__ ULL add2(ULL a, ULL b) {
    ULL r; asm("add.rn.f32x2 %0, %1, %2;" : "=l"(r) : "l"(a), "l"(b)); return r;
}

// ===================== Kernel A: weighted segment-sum (HBM stream) ==========
__global__ __launch_bounds__(256)
void fs_phase1(const float* __restrict__ E_S, const float* __restrict__ W,
               const int* __restrict__ part_idx)
{
    __shared__ float w_s[2 * KK];
    __shared__ float winv_s[2 * PP];
    __shared__ int   pidx_s[KK];

    const int tid = threadIdx.x;
    const int bx  = blockIdx.x;
    const int row0 = bx * 2;

    if (tid < KK)  pidx_s[tid] = part_idx[tid];
    if (tid < 2 * KK) w_s[tid] = W[(size_t)row0 * KK + tid];
    __syncthreads();
    if (tid < 2 * PP) {
        int r = tid >> 2, p = tid & 3;
        float s = 0.f;
#pragma unroll
        for (int kp = 0; kp < KPP; kp++) s += w_s[r * KK + pidx_s[p * KPP + kp]];
        winv_s[tid] = 1.0f / (s + 1e-6f);
    }
    __syncthreads();

    const int p0 = tid >> 6;
    const int d4 = tid & 63;
    const float4* Ea = (const float4*)(E_S + (size_t)row0 * KK * DD);
    const float4* Eb = Ea + (KK * DD / 4);

    float4 aa = make_float4(0.f,0.f,0.f,0.f);
    float4 ab = make_float4(0.f,0.f,0.f,0.f);
#pragma unroll
    for (int kp = 0; kp < KPP; kp++) {
        const int k  = pidx_s[p0 * KPP + kp];
        const float wa = w_s[k];
        const float wb = w_s[KK + k];
        const float4 ea = Ea[k * 64 + d4];
        const float4 eb = Eb[k * 64 + d4];
        aa.x = fmaf(wa, ea.x, aa.x); aa.y = fmaf(wa, ea.y, aa.y);
        aa.z = fmaf(wa, ea.z, aa.z); aa.w = fmaf(wa, ea.w, aa.w);
        ab.x = fmaf(wb, eb.x, ab.x); ab.y = fmaf(wb, eb.y, ab.y);
        ab.z = fmaf(wb, eb.z, ab.z); ab.w = fmaf(wb, eb.w, ab.w);
    }
    const float iva = winv_s[p0];
    const float ivb = winv_s[PP + p0];

    float4 s0 = make_float4(aa.x * iva, ab.x * ivb, aa.y * iva, ab.y * ivb);
    float4 s1 = make_float4(aa.z * iva, ab.z * ivb, aa.w * iva, ab.w * ivb);

    const size_t group = bx >> 3;
    const int    r2g   = bx & 7;
    float4* out4 = ((float4*)u_scratch) + group * 4096 + (size_t)(p0 * 8 + r2g) * 128 + d4 * 2;
    out4[0] = s0;
    out4[1] = s1;
}

// ===================== Kernel B: register-blocked FFMA2 GEMMs ===============
// smem: u_ull[4][8][256] ULL (64KB) | S_s[8][256] ULL (16KB) | alpha[64]f | red[256]f
#define SMEMB_BYTES (8192 * 8 + 2048 * 8 + (64 + 256) * 4)

__global__ __launch_bounds__(THREADS)
void fs_phase2(const float* __restrict__ part_W, const float* __restrict__ part_b,
               const float* __restrict__ v, const float* __restrict__ c,
               const float* __restrict__ ln_g, const float* __restrict__ ln_b,
               const float* __restrict__ proj_W, const float* __restrict__ proj_b,
               const float* __restrict__ out_g, const float* __restrict__ out_b,
               float* __restrict__ out)
{
    extern __shared__ ULL u_ull[];                 // [P][8][256]
    ULL*   S_s     = u_ull + 8192;                 // [8][256]
    float* alpha_s = (float*)(S_s + 2048);         // [16][4]
    float* red_s   = alpha_s + 64;                 // [16][8][2]

    const int tid = threadIdx.x;
    const int bt0 = blockIdx.x * ROWS;

    const int h = tid >> 7;          // row-pair half (rowpairs h*4 .. h*4+3)
    const int g = (tid >> 2) & 31;   // column group (8 cols)
    const int k = tid & 3;           // K-split lane (interleaved)

    // ---- stage u tile (L2-hot) into smem ----
    {
        const float4* gsrc = ((const float4*)u_scratch) + (size_t)blockIdx.x * 4096;
        float4* u4s = (float4*)u_ull;
#pragma unroll
        for (int n = 0; n < 16; n++) u4s[tid + n * 256] = gsrc[tid + n * 256];
    }
    __syncthreads();

    // ---- 2a: per-part linear, register-tiled (4rp x 8col), K interleave x4 --
#pragma unroll 1
    for (int p = 0; p < PP; p++) {
        ULL acc[4][8];
#pragma unroll
        for (int cc = 0; cc < 8; cc++) {
            const float b = (k == 0) ? part_b[p * DD + g * 8 + cc] : 0.f;
            const ULL bp = pack2(b, b);
#pragma unroll
            for (int rp = 0; rp < 4; rp++) acc[rp][cc] = bp;
        }

        const ULL*   ub = u_ull + (p * 8 + h * 4) * 256;
        const float* wb = part_W + (size_t)p * DD * DD + (size_t)(g * 8) * DD;

#pragma unroll 4
        for (int ii = 0; ii < 32; ii++) {
            const int ip = k + 4 * ii;           // i-pair, i = 2*ip
            ulonglong2 uv[4];
#pragma unroll
            for (int rp = 0; rp < 4; rp++)
                uv[rp] = *(const ulonglong2*)(ub + rp * 256 + 2 * ip);
#pragma unroll
            for (int cc = 0; cc < 8; cc++) {
                const float2 wv = *(const float2*)(wb + cc * DD + 2 * ip);
                const ULL w0 = pack2(wv.x, wv.x);
                const ULL w1 = pack2(wv.y, wv.y);
#pragma unroll
                for (int rp = 0; rp < 4; rp++) {
                    fma2(acc[rp][cc], uv[rp].x, w0);
                    fma2(acc[rp][cc], uv[rp].y, w1);
                }
            }
        }
        // K-split reduction over the 4 lanes (xor 1, xor 2)
#pragma unroll
        for (int rp = 0; rp < 4; rp++)
#pragma unroll
            for (int cc = 0; cc < 8; cc++) {
                acc[rp][cc] = add2(acc[rp][cc], __shfl_xor_sync(0xffffffffu, acc[rp][cc], 1));
                acc[rp][cc] = add2(acc[rp][cc], __shfl_xor_sync(0xffffffffu, acc[rp][cc], 2));
            }
        __syncthreads();
        {   // lane k writes rowpair h*4+k
            ULL* dst = u_ull + (p * 8 + h * 4 + k) * 256 + g * 8;
#pragma unroll
            for (int cc = 0; cc < 8; cc++) dst[cc] = acc[k][cc];
        }
        __syncthreads();
    }

    // ---- 2b: LN stats + sigmoid gate per (row, part); one warp per pair ----
    {
        const int wid = tid >> 5, lane = tid & 31;
        const float* uh = (const float*)u_ull;
#pragma unroll 1
        for (int j = 0; j < 8; j++) {
            const int pair = wid * 8 + j;
            const int r = pair >> 2, p = pair & 3;
            const int base = ((p * 8 + (r >> 1)) * 256) * 2 + (r & 1);
            float s1 = 0.f, s2 = 0.f, s3 = 0.f, s4 = 0.f, s5 = 0.f;
#pragma unroll
            for (int i = 0; i < DD / 32; i++) {
                const int col = lane + i * 32;
                const float x  = uh[base + col * 2];
                const float vv = v[p * DD + col];
                const float gv = ln_g[p * DD + col] * vv;
                const float bv = ln_b[p * DD + col] * vv;
                s1 += x; s2 += x * x; s3 += x * gv; s4 += gv; s5 += bv;
            }
#pragma unroll
            for (int off = 16; off; off >>= 1) {
                s1 += __shfl_xor_sync(0xffffffffu, s1, off);
                s2 += __shfl_xor_sync(0xffffffffu, s2, off);
                s3 += __shfl_xor_sync(0xffffffffu, s3, off);
                s4 += __shfl_xor_sync(0xffffffffu, s4, off);
                s5 += __shfl_xor_sync(0xffffffffu, s5, off);
            }
            if (lane == 0) {
                const float m   = s1 * (1.0f / DD);
                const float var = s2 * (1.0f / DD) - m * m;
                const float rs  = rsqrtf(var + 1e-5f);
                const float dot = rs * (s3 - m * s4) + s5 + c[p];
                alpha_s[r * PP + p] = 1.0f / (1.0f + __expf(-dot));
            }
        }
    }
    __syncthreads();

    // ---- scale u_hat by alpha in place ----
#pragma unroll
    for (int p = 0; p < PP; p++) {
#pragma unroll
        for (int r2 = 0; r2 < 8; r2++) {
            const ULL ap = pack2(alpha_s[(2 * r2) * PP + p], alpha_s[(2 * r2 + 1) * PP + p]);
            const int idx = (p * 8 + r2) * 256 + tid;
            u_ull[idx] = mul2(u_ull[idx], ap);
        }
    }
    __syncthreads();

    // ---- 2c: projection, register-tiled (4rp x 8col), K interleave x4 ------
    {
        ULL acc[4][8];
#pragma unroll
        for (int cc = 0; cc < 8; cc++) {
            const float b = (k == 0) ? proj_b[g * 8 + cc] : 0.f;
            const ULL bp = pack2(b, b);
#pragma unroll
            for (int rp = 0; rp < 4; rp++) acc[rp][cc] = bp;
        }

#pragma unroll 1
        for (int p = 0; p < PP; p++) {
            const ULL*   zb = u_ull + (p * 8 + h * 4) * 256;
            const float* wb = proj_W + (size_t)(g * 8) * COLS + p * DD;
#pragma unroll 4
            for (int ii = 0; ii < 32; ii++) {
                const int ip = k + 4 * ii;
                ulonglong2 uv[4];
#pragma unroll
                for (int rp = 0; rp < 4; rp++)
                    uv[rp] = *(const ulonglong2*)(zb + rp * 256 + 2 * ip);
#pragma unroll
                for (int cc = 0; cc < 8; cc++) {
                    const float2 wv = *(const float2*)(wb + (size_t)cc * COLS + 2 * ip);
                    const ULL w0 = pack2(wv.x, wv.x);
                    const ULL w1 = pack2(wv.y, wv.y);
#pragma unroll
                    for (int rp = 0; rp < 4; rp++) {
                        fma2(acc[rp][cc], uv[rp].x, w0);
                        fma2(acc[rp][cc], uv[rp].y, w1);
                    }
                }
            }
        }
#pragma unroll
        for (int rp = 0; rp < 4; rp++)
#pragma unroll
            for (int cc = 0; cc < 8; cc++) {
                acc[rp][cc] = add2(acc[rp][cc], __shfl_xor_sync(0xffffffffu, acc[rp][cc], 1));
                acc[rp][cc] = add2(acc[rp][cc], __shfl_xor_sync(0xffffffffu, acc[rp][cc], 2));
            }
        {   // lane k writes rowpair h*4+k of S
            ULL* dst = S_s + (h * 4 + k) * 256 + g * 8;
#pragma unroll
            for (int cc = 0; cc < 8; cc++) dst[cc] = acc[k][cc];
        }
    }
    __syncthreads();

    // ---- 2d: final LayerNorm across D (thread = column) ----
    {
        float x[ROWS];
#pragma unroll
        for (int r2 = 0; r2 < 8; r2++) unpack2(S_s[r2 * 256 + tid], x[2 * r2], x[2 * r2 + 1]);

        const int wid = tid >> 5, lane = tid & 31;
#pragma unroll
        for (int r = 0; r < ROWS; r++) {
            float s1 = x[r];
            float s2 = x[r] * x[r];
#pragma unroll
            for (int off = 16; off; off >>= 1) {
                s1 += __shfl_xor_sync(0xffffffffu, s1, off);
                s2 += __shfl_xor_sync(0xffffffffu, s2, off);
            }
            if (lane == 0) {
                red_s[(r * 8 + wid) * 2 + 0] = s1;
                red_s[(r * 8 + wid) * 2 + 1] = s2;
            }
        }
        __syncthreads();
        const float og = out_g[tid], ob = out_b[tid];
#pragma unroll
        for (int r = 0; r < ROWS; r++) {
            float s1 = 0.f, s2 = 0.f;
#pragma unroll
            for (int w = 0; w < 8; w++) {
                s1 += red_s[(r * 8 + w) * 2 + 0];
                s2 += red_s[(r * 8 + w) * 2 + 1];
            }
            const float m   = s1 * (1.0f / DD);
            const float var = s2 * (1.0f / DD) - m * m;
            const float rs  = rsqrtf(var + 1e-5f);
            out[(size_t)(bt0 + r) * DD + tid] = (x[r] - m) * rs * og + ob;
        }
    }
}

extern "C" void kernel_launch(void* const* d_in, const int* in_sizes, int n_in,
                              void* d_out, int out_size)
{
    (void)in_sizes; (void)n_in; (void)out_size;
    const float* E_S    = (const float*)d_in[0];
    const float* W      = (const float*)d_in[1];
    const int*   pidx   = (const int*)  d_in[2];
    const float* part_W = (const float*)d_in[3];
    const float* part_b = (const float*)d_in[4];
    const float* v      = (const float*)d_in[5];
    const float* c      = (const float*)d_in[6];
    const float* ln_g   = (const float*)d_in[7];
    const float* ln_b   = (const float*)d_in[8];
    const float* proj_W = (const float*)d_in[9];
    const float* proj_b = (const float*)d_in[10];
    const float* out_g  = (const float*)d_in[11];
    const float* out_b  = (const float*)d_in[12];
    float* out = (float*)d_out;

    fs_phase1<<<BT / 2, 256>>>(E_S, W, pidx);

    cudaFuncSetAttribute(fs_phase2, cudaFuncAttributeMaxDynamicSharedMemorySize, SMEMB_BYTES);
    fs_phase2<<<BT / ROWS, THREADS, SMEMB_BYTES>>>(
        part_W, part_b, v, c, ln_g, ln_b,
        proj_W, proj_b, out_g, out_b, out);
}

// round 5
// speedup vs baseline: 1.5593x; 1.5576x over previous
#include <cuda_runtime.h>
#include <math.h>

#define BT      4096
#define KK      64
#define DD      256
#define PP      4
#define KPP     16
#define ROWS    16
#define THREADS 256
#define WST     257

typedef unsigned long long ULL;

__device__ __align__(16) float u_scratch[(size_t)BT * 1024];

__device__ __forceinline__ void fma2(ULL &acc, ULL a, ULL b) {
    asm("fma.rn.f32x2 %0, %1, %2, %0;" : "+l"(acc) : "l"(a), "l"(b));
}
__device__ __forceinline__ ULL pack2(float lo, float hi) {
    ULL r; asm("mov.b64 %0, {%1, %2};" : "=l"(r) : "f"(lo), "f"(hi)); return r;
}
__device__ __forceinline__ void unpack2(ULL a, float &lo, float &hi) {
    asm("mov.b64 {%0, %1}, %2;" : "=f"(lo), "=f"(hi) : "l"(a));
}
__device__ __forceinline__ ULL mul2(ULL a, ULL b) {
    ULL r; asm("mul.rn.f32x2 %0, %1, %2;" : "=l"(r) : "l"(a), "l"(b)); return r;
}
__device__ __forceinline__ ULL add2(ULL a, ULL b) {
    ULL r; asm("add.rn.f32x2 %0, %1, %2;" : "=l"(r) : "l"(a), "l"(b)); return r;
}

// ===================== Kernel A: weighted segment-sum (HBM stream) ==========
__global__ __launch_bounds__(256)
void fs_phase1(const float* __restrict__ E_S, const float* __restrict__ W,
               const int* __restrict__ part_idx)
{
    __shared__ float w_s[2 * KK];
    __shared__ float winv_s[2 * PP];
    __shared__ int   pidx_s[KK];

    const int tid = threadIdx.x;
    const int bx  = blockIdx.x;
    const int row0 = bx * 2;

    if (tid < KK)  pidx_s[tid] = part_idx[tid];
    if (tid < 2 * KK) w_s[tid] = W[(size_t)row0 * KK + tid];
    __syncthreads();
    if (tid < 2 * PP) {
        int r = tid >> 2, p = tid & 3;
        float s = 0.f;
#pragma unroll
        for (int kp = 0; kp < KPP; kp++) s += w_s[r * KK + pidx_s[p * KPP + kp]];
        winv_s[tid] = 1.0f / (s + 1e-6f);
    }
    __syncthreads();

    const int p0 = tid >> 6;
    const int d4 = tid & 63;
    const float4* Ea = (const float4*)(E_S + (size_t)row0 * KK * DD);
    const float4* Eb = Ea + (KK * DD / 4);

    float4 aa = make_float4(0.f,0.f,0.f,0.f);
    float4 ab = make_float4(0.f,0.f,0.f,0.f);
#pragma unroll
    for (int kp = 0; kp < KPP; kp++) {
        const int k  = pidx_s[p0 * KPP + kp];
        const float wa = w_s[k];
        const float wb = w_s[KK + k];
        const float4 ea = Ea[k * 64 + d4];
        const float4 eb = Eb[k * 64 + d4];
        aa.x = fmaf(wa, ea.x, aa.x); aa.y = fmaf(wa, ea.y, aa.y);
        aa.z = fmaf(wa, ea.z, aa.z); aa.w = fmaf(wa, ea.w, aa.w);
        ab.x = fmaf(wb, eb.x, ab.x); ab.y = fmaf(wb, eb.y, ab.y);
        ab.z = fmaf(wb, eb.z, ab.z); ab.w = fmaf(wb, eb.w, ab.w);
    }
    const float iva = winv_s[p0];
    const float ivb = winv_s[PP + p0];

    float4 s0 = make_float4(aa.x * iva, ab.x * ivb, aa.y * iva, ab.y * ivb);
    float4 s1 = make_float4(aa.z * iva, ab.z * ivb, aa.w * iva, ab.w * ivb);

    const size_t group = bx >> 3;
    const int    r2g   = bx & 7;
    float4* out4 = ((float4*)u_scratch) + group * 4096 + (size_t)(p0 * 8 + r2g) * 128 + d4 * 2;
    out4[0] = s0;
    out4[1] = s1;
}

// ===================== Kernel B: staged-weight FFMA2 GEMM ===================
// smem: u[8192] ULL | red[8192] ULL | wt[32*257] f | alpha[64] f | redf[256] f
#define SMEMB_BYTES (8192*8 + 8192*8 + 32*WST*4 + 64*4 + 256*4)

// tile T: 0..31 = part_W (p=T>>3), 32..63 = proj_W
__device__ __forceinline__ void ldg_tile(float4 pf[8], int T,
                                         const float* __restrict__ pw,
                                         const float* __restrict__ qw,
                                         int w, int lane) {
    const float* base; int rstride, off0;
    if (T < 32) { base = pw + (size_t)(T >> 3) * (DD * DD); rstride = DD;   off0 = (T & 7) * 32; }
    else        { base = qw;                                 rstride = 1024; off0 = (T - 32) * 32; }
    const int koff = (lane & 7) * 4;
    const int osub = w * 4 + (lane >> 3);
#pragma unroll
    for (int it = 0; it < 8; it++) {
        const int o = it * 32 + osub;
        pf[it] = *(const float4*)(base + (size_t)o * rstride + off0 + koff);
    }
}
__device__ __forceinline__ void sts_tile(float* wt, const float4 pf[8], int w, int lane) {
    const int koff = (lane & 7) * 4;
    const int osub = w * 4 + (lane >> 3);
#pragma unroll
    for (int it = 0; it < 8; it++) {
        const int o = it * 32 + osub;
        wt[(koff + 0) * WST + o] = pf[it].x;
        wt[(koff + 1) * WST + o] = pf[it].y;
        wt[(koff + 2) * WST + o] = pf[it].z;
        wt[(koff + 3) * WST + o] = pf[it].w;
    }
}
__device__ __forceinline__ void compute_tile(ULL acc[4][8], const ULL* ub,
                                             const float* wt, int ks, int lane) {
#pragma unroll
    for (int k2 = 0; k2 < 4; k2++) {
        const int kl = ks * 8 + 2 * k2;
        ulonglong2 uv[4];
#pragma unroll
        for (int rp = 0; rp < 4; rp++) uv[rp] = *(const ulonglong2*)(ub + rp * 256 + kl);
        const float* w0p = wt + kl * WST + lane;
        const float* w1p = w0p + WST;
#pragma unroll
        for (int cc = 0; cc < 8; cc++) {
            const float a0 = w0p[cc * 32], a1 = w1p[cc * 32];
            const ULL W0 = pack2(a0, a0);
            const ULL W1 = pack2(a1, a1);
#pragma unroll
            for (int rp = 0; rp < 4; rp++) {
                fma2(acc[rp][cc], uv[rp].x, W0);
                fma2(acc[rp][cc], uv[rp].y, W1);
            }
        }
    }
}

__global__ __launch_bounds__(THREADS, 1)
void fs_phase2(const float* __restrict__ part_W, const float* __restrict__ part_b,
               const float* __restrict__ v, const float* __restrict__ c,
               const float* __restrict__ ln_g, const float* __restrict__ ln_b,
               const float* __restrict__ proj_W, const float* __restrict__ proj_b,
               const float* __restrict__ out_g, const float* __restrict__ out_b,
               float* __restrict__ out)
{
    extern __shared__ char smraw[];
    ULL*   u       = (ULL*)smraw;              // [4*8*256]
    ULL*   red     = u + 8192;                 // [4][2048]
    float* wt      = (float*)(red + 8192);     // [32][WST]
    float* alpha_s = wt + 32 * WST;            // [64]
    float* redf    = alpha_s + 64;             // [256]

    const int tid  = threadIdx.x;
    const int w    = tid >> 5, lane = tid & 31;
    const int rg   = w & 1,   ks   = w >> 1;
    const int bt0  = blockIdx.x * ROWS;

    // stage u tile (L2-hot, already packed row-pairs [p][rp][i])
    {
        const float4* gsrc = ((const float4*)u_scratch) + (size_t)blockIdx.x * 4096;
        float4* u4 = (float4*)u;
#pragma unroll
        for (int n = 0; n < 16; n++) u4[tid + n * 256] = gsrc[tid + n * 256];
    }

    float4 pf[8];
    ldg_tile(pf, 0, part_W, proj_W, w, lane);
    __syncthreads();                    // u ready
    sts_tile(wt, pf, w, lane);
    __syncthreads();                    // wt(0) ready

    ULL acc[4][8];
#pragma unroll
    for (int rp = 0; rp < 4; rp++)
#pragma unroll
        for (int cc = 0; cc < 8; cc++) acc[rp][cc] = 0ull;

#pragma unroll 1
    for (int T = 0; T < 64; T++) {
        if (T < 63) ldg_tile(pf, T + 1, part_W, proj_W, w, lane);

        const int Tl = (T < 32) ? T : T - 32;
        const ULL* ub = u + ((Tl >> 3) * 8 + rg * 4) * 256 + (Tl & 7) * 32;
        compute_tile(acc, ub, wt, ks, lane);

        const bool g1end = (T < 32) && ((T & 7) == 7);
        if (g1end || T == 63) {
            // write K-split partials, reset accumulators
#pragma unroll
            for (int rp = 0; rp < 4; rp++) {
                ULL* dst = red + ks * 2048 + (rg * 4 + rp) * 256 + lane;
#pragma unroll
                for (int cc = 0; cc < 8; cc++) { dst[cc * 32] = acc[rp][cc]; acc[rp][cc] = 0ull; }
            }
            __syncthreads();
            // combine 4 partials + bias
            if (T < 32) {
                const int p = T >> 3;
#pragma unroll
                for (int j = 0; j < 8; j++) {
                    const int idx = tid + j * 256;
                    const float b = part_b[p * DD + (idx & 255)];
                    ULL s = add2(add2(red[idx], red[2048 + idx]),
                                 add2(red[4096 + idx], red[6144 + idx]));
                    u[p * 2048 + idx] = add2(s, pack2(b, b));
                }
            } else {
#pragma unroll
                for (int j = 0; j < 8; j++) {
                    const int idx = tid + j * 256;
                    const float b = proj_b[idx & 255];
                    ULL s = add2(add2(red[idx], red[2048 + idx]),
                                 add2(red[4096 + idx], red[6144 + idx]));
                    red[idx] = add2(s, pack2(b, b));
                }
            }
            __syncthreads();

            if (T == 31) {
                // LN stats + sigmoid gate per (row, part); one warp per pair
                const float* uh = (const float*)u;
#pragma unroll 1
                for (int j = 0; j < 8; j++) {
                    const int pair = w * 8 + j;
                    const int r = pair >> 2, p = pair & 3;
                    const int base = ((p * 8 + (r >> 1)) * 256) * 2 + (r & 1);
                    float s1 = 0.f, s2 = 0.f, s3 = 0.f, s4 = 0.f, s5 = 0.f;
#pragma unroll
                    for (int i = 0; i < DD / 32; i++) {
                        const int col = lane + i * 32;
                        const float x  = uh[base + col * 2];
                        const float vv = v[p * DD + col];
                        const float gv = ln_g[p * DD + col] * vv;
                        const float bv = ln_b[p * DD + col] * vv;
                        s1 += x; s2 += x * x; s3 += x * gv; s4 += gv; s5 += bv;
                    }
#pragma unroll
                    for (int off = 16; off; off >>= 1) {
                        s1 += __shfl_xor_sync(0xffffffffu, s1, off);
                        s2 += __shfl_xor_sync(0xffffffffu, s2, off);
                        s3 += __shfl_xor_sync(0xffffffffu, s3, off);
                        s4 += __shfl_xor_sync(0xffffffffu, s4, off);
                        s5 += __shfl_xor_sync(0xffffffffu, s5, off);
                    }
                    if (lane == 0) {
                        const float m   = s1 * (1.0f / DD);
                        const float var = s2 * (1.0f / DD) - m * m;
                        const float rs  = rsqrtf(var + 1e-5f);
                        const float dot = rs * (s3 - m * s4) + s5 + c[p];
                        alpha_s[r * PP + p] = 1.0f / (1.0f + __expf(-dot));
                    }
                }
                __syncthreads();
                // scale u_hat by alpha -> Z
#pragma unroll
                for (int p = 0; p < PP; p++)
#pragma unroll
                    for (int r2 = 0; r2 < 8; r2++) {
                        const ULL ap = pack2(alpha_s[(2 * r2) * PP + p],
                                             alpha_s[(2 * r2 + 1) * PP + p]);
                        const int idx = (p * 8 + r2) * 256 + tid;
                        u[idx] = mul2(u[idx], ap);
                    }
                __syncthreads();
            }
        }
        if (T < 63) { __syncthreads(); sts_tile(wt, pf, w, lane); __syncthreads(); }
    }

    // ---- final LayerNorm across D (S lives in red[rp*256+col]) ----
    {
        float x[ROWS];
#pragma unroll
        for (int r2 = 0; r2 < 8; r2++) unpack2(red[r2 * 256 + tid], x[2 * r2], x[2 * r2 + 1]);

#pragma unroll
        for (int r = 0; r < ROWS; r++) {
            float s1 = x[r];
            float s2 = x[r] * x[r];
#pragma unroll
            for (int off = 16; off; off >>= 1) {
                s1 += __shfl_xor_sync(0xffffffffu, s1, off);
                s2 += __shfl_xor_sync(0xffffffffu, s2, off);
            }
            if (lane == 0) {
                redf[(r * 8 + w) * 2 + 0] = s1;
                redf[(r * 8 + w) * 2 + 1] = s2;
            }
        }
        __syncthreads();
        const float og = out_g[tid], ob = out_b[tid];
#pragma unroll
        for (int r = 0; r < ROWS; r++) {
            float s1 = 0.f, s2 = 0.f;
#pragma unroll
            for (int ww = 0; ww < 8; ww++) {
                s1 += redf[(r * 8 + ww) * 2 + 0];
                s2 += redf[(r * 8 + ww) * 2 + 1];
            }
            const float m   = s1 * (1.0f / DD);
            const float var = s2 * (1.0f / DD) - m * m;
            const float rs  = rsqrtf(var + 1e-5f);
            out[(size_t)(bt0 + r) * DD + tid] = (x[r] - m) * rs * og + ob;
        }
    }
}

extern "C" void kernel_launch(void* const* d_in, const int* in_sizes, int n_in,
                              void* d_out, int out_size)
{
    (void)in_sizes; (void)n_in; (void)out_size;
    const float* E_S    = (const float*)d_in[0];
    const float* W      = (const float*)d_in[1];
    const int*   pidx   = (const int*)  d_in[2];
    const float* part_W = (const float*)d_in[3];
    const float* part_b = (const float*)d_in[4];
    const float* v      = (const float*)d_in[5];
    const float* c      = (const float*)d_in[6];
    const float* ln_g   = (const float*)d_in[7];
    const float* ln_b   = (const float*)d_in[8];
    const float* proj_W = (const float*)d_in[9];
    const float* proj_b = (const float*)d_in[10];
    const float* out_g  = (const float*)d_in[11];
    const float* out_b  = (const float*)d_in[12];
    float* out = (float*)d_out;

    fs_phase1<<<BT / 2, 256>>>(E_S, W, pidx);

    cudaFuncSetAttribute(fs_phase2, cudaFuncAttributeMaxDynamicSharedMemorySize, SMEMB_BYTES);
    fs_phase2<<<BT / ROWS, THREADS, SMEMB_BYTES>>>(
        part_W, part_b, v, c, ln_g, ln_b,
        proj_W, proj_b, out_g, out_b, out);
}